// round 1
// baseline (speedup 1.0000x reference)
#include <cuda_runtime.h>

#define V 8192
#define E 262144
#define D 128
#define IDXBITS 18
#define IDXMASK 0x3FFFFu

// ---------------- scratch (device globals; no allocations allowed) ----------
__device__ float    g_hw[V * D];      // h @ W^T             (4 MB, L2-resident)
__device__ float    g_s1[V];          // hw[v] . att[:128]
__device__ float    g_s2[V];          // hw[v] . att[128:]
__device__ float    g_S[D];           // column sum of hw
__device__ int      g_hist[V];        // per-src edge counts
__device__ int      g_cur[V];         // scatter cursors
__device__ int      g_off[V + 1];     // CSR offsets
__device__ unsigned g_meta[E];        // (dst<<18) | orig_edge_idx, sorted by src
__device__ float    g_w[E];           // expm1(leakyrelu(logit)), sorted by src
__device__ int      g_is64;           // edge_index dtype flag

// --------------- detect int64 vs int32 edge_index ---------------------------
// If data is little-endian int64 (values < 2^13), every odd 32-bit word is 0.
// If int32, odd words are random src values; P(256 of them all zero) ~ 8192^-256.
__global__ void k_detect(const int* __restrict__ e32) {
    __shared__ int flag;
    if (threadIdx.x == 0) flag = 0;
    __syncthreads();
    if (e32[2 * threadIdx.x + 1] != 0) atomicExch(&flag, 1);
    __syncthreads();
    if (threadIdx.x == 0) g_is64 = (flag == 0) ? 1 : 0;
}

__global__ void k_init() {
    int i = blockIdx.x * blockDim.x + threadIdx.x;
    if (i < V) { g_hist[i] = 0; g_cur[i] = 0; }
    if (i < D) g_S[i] = 0.f;
}

// --------------- hw = h @ W^T  (fp32 SIMT, shared-staged tiles) --------------
__global__ void __launch_bounds__(128) k_hw(const float* __restrict__ h,
                                            const float* __restrict__ Wm) {
    __shared__ float sh_h[8][128];       // 8 input rows
    __shared__ float sh_wt[32][129];     // W tile transposed: [k][outcol], padded
    int c = threadIdx.x;                 // output column
    int row0 = blockIdx.x * 8;
    {
        const float4* h4 = (const float4*)(h + (size_t)row0 * D);
        float4* s4 = (float4*)&sh_h[0][0];
#pragma unroll
        for (int i = 0; i < 2; i++) s4[c + i * 128] = h4[c + i * 128];
    }
    float acc[8] = {0, 0, 0, 0, 0, 0, 0, 0};
    for (int k0 = 0; k0 < 128; k0 += 32) {
        __syncthreads();
#pragma unroll
        for (int it = 0; it < 8; it++) {
            int i = c + it * 128;        // 0..1023 over the 128x32 tile (as float4)
            int r = i >> 3;              // W row (= output col) 0..127
            int q = i & 7;               // float4 index within 32 k's
            float4 wv = *(const float4*)(Wm + (size_t)r * D + k0 + q * 4);
            sh_wt[q * 4 + 0][r] = wv.x;
            sh_wt[q * 4 + 1][r] = wv.y;
            sh_wt[q * 4 + 2][r] = wv.z;
            sh_wt[q * 4 + 3][r] = wv.w;
        }
        __syncthreads();
#pragma unroll
        for (int kk = 0; kk < 32; kk += 4) {
            float w0 = sh_wt[kk + 0][c];
            float w1 = sh_wt[kk + 1][c];
            float w2 = sh_wt[kk + 2][c];
            float w3 = sh_wt[kk + 3][c];
#pragma unroll
            for (int r = 0; r < 8; r++) {
                float4 h4v = *(const float4*)&sh_h[r][k0 + kk];
                acc[r] += h4v.x * w0;
                acc[r] += h4v.y * w1;
                acc[r] += h4v.z * w2;
                acc[r] += h4v.w * w3;
            }
        }
    }
#pragma unroll
    for (int r = 0; r < 8; r++) g_hw[(size_t)(row0 + r) * D + c] = acc[r];
}

// --------------- per-node attention halves: s1, s2 ---------------------------
__global__ void __launch_bounds__(256) k_s(const float* __restrict__ att) {
    int gw = (blockIdx.x * 256 + threadIdx.x) >> 5;   // node = global warp
    int lane = threadIdx.x & 31;
    float4 hv = *(const float4*)(g_hw + (size_t)gw * D + lane * 4);
    float4 a1 = *(const float4*)(att + lane * 4);
    float4 a2 = *(const float4*)(att + D + lane * 4);
    float s1 = hv.x * a1.x + hv.y * a1.y + hv.z * a1.z + hv.w * a1.w;
    float s2 = hv.x * a2.x + hv.y * a2.y + hv.z * a2.z + hv.w * a2.w;
#pragma unroll
    for (int o = 16; o; o >>= 1) {
        s1 += __shfl_xor_sync(0xffffffffu, s1, o);
        s2 += __shfl_xor_sync(0xffffffffu, s2, o);
    }
    if (!lane) { g_s1[gw] = s1; g_s2[gw] = s2; }
}

// --------------- S = column sum of hw ---------------------------------------
__global__ void k_colsum() {
    int c = threadIdx.x;
    int r0 = blockIdx.x * 128;
    float s = 0.f;
#pragma unroll 8
    for (int r = 0; r < 128; r++) s += g_hw[(size_t)(r0 + r) * D + c];
    atomicAdd(&g_S[c], s);
}

// --------------- counting sort of edges by src -------------------------------
__global__ void k_hist(const int* __restrict__ e32) {
    int e = blockIdx.x * blockDim.x + threadIdx.x;
    if (e >= E) return;
    int src = g_is64 ? e32[2 * e] : e32[e];
    atomicAdd(&g_hist[src], 1);
}

__global__ void __launch_bounds__(1024) k_scan() {
    __shared__ int sh[1024];
    int t = threadIdx.x;
    int loc[8];
    int s = 0;
#pragma unroll
    for (int i = 0; i < 8; i++) { loc[i] = g_hist[t * 8 + i]; s += loc[i]; }
    sh[t] = s;
    __syncthreads();
    for (int o = 1; o < 1024; o <<= 1) {
        int v = (t >= o) ? sh[t - o] : 0;
        __syncthreads();
        sh[t] += v;
        __syncthreads();
    }
    int run = sh[t] - s;  // exclusive prefix
#pragma unroll
    for (int i = 0; i < 8; i++) { g_off[t * 8 + i] = run; run += loc[i]; }
    if (t == 1023) g_off[V] = run;
}

__global__ void k_scatter(const int* __restrict__ e32) {
    int e = blockIdx.x * blockDim.x + threadIdx.x;
    if (e >= E) return;
    int src, dst;
    if (g_is64) { src = e32[2 * e]; dst = e32[2 * (E + e)]; }
    else        { src = e32[e];     dst = e32[E + e]; }
    float a = g_s1[src] + g_s2[dst];
    a = a > 0.f ? a : 0.2f * a;                 // LeakyReLU(0.2)
    float w = expm1f(a);                        // exp(a) - 1
    int pos = g_off[src] + atomicAdd(&g_cur[src], 1);
    g_meta[pos] = ((unsigned)dst << IDXBITS) | (unsigned)e;
    g_w[pos] = w;
}

// --------------- per-row: dedup (last-write-wins) + gather-accumulate --------
__global__ void __launch_bounds__(256) k_row(float* __restrict__ out) {
    __shared__ unsigned sm_meta[8][256];
    __shared__ float    sm_w[8][256];
    int wid = threadIdx.x >> 5, lane = threadIdx.x & 31;
    int row = blockIdx.x * 8 + wid;
    int beg = g_off[row];
    int d = g_off[row + 1] - beg;
    float4 acc = make_float4(0.f, 0.f, 0.f, 0.f);
    float dsum = 0.f;

    if (d <= 256) {
        for (int t = lane; t < d; t += 32) {
            sm_meta[wid][t] = g_meta[beg + t];
            sm_w[wid][t] = g_w[beg + t];
        }
        __syncwarp();
        // pass 1: dedup — keep only max orig-idx per dst (reference last-write-wins)
        for (int base = 0; base < d; base += 32) {
            int j = base + lane;
            if (j < d) {
                unsigned m = sm_meta[wid][j];
                unsigned dst = m >> IDXBITS, idx = m & IDXMASK;
                bool kept = true;
                for (int t = 0; t < d; t++) {
                    unsigned m2 = sm_meta[wid][t];
                    if ((m2 >> IDXBITS) == dst && (m2 & IDXMASK) > idx) { kept = false; break; }
                }
                float wk = kept ? sm_w[wid][j] : 0.f;
                sm_w[wid][j] = wk;
                dsum += wk;
            }
        }
        __syncwarp();
        // pass 2: coalesced 512B gathers of hw[dst] (L2-resident), rank-1 updates
        int t = 0;
        for (; t + 4 <= d; t += 4) {
#pragma unroll
            for (int u = 0; u < 4; u++) {
                float wv = sm_w[wid][t + u];
                unsigned dv = sm_meta[wid][t + u] >> IDXBITS;
                if (wv != 0.f) {
                    float4 hv = *(const float4*)(g_hw + (size_t)dv * D + lane * 4);
                    acc.x += wv * hv.x; acc.y += wv * hv.y;
                    acc.z += wv * hv.z; acc.w += wv * hv.w;
                }
            }
        }
        for (; t < d; t++) {
            float wv = sm_w[wid][t];
            unsigned dv = sm_meta[wid][t] >> IDXBITS;
            if (wv != 0.f) {
                float4 hv = *(const float4*)(g_hw + (size_t)dv * D + lane * 4);
                acc.x += wv * hv.x; acc.y += wv * hv.y;
                acc.z += wv * hv.z; acc.w += wv * hv.w;
            }
        }
    } else {
        // safety fallback for pathological degree (> 256): O(d^2/32) from global
        for (int t = 0; t < d; t++) {
            unsigned m = g_meta[beg + t];
            unsigned dst = m >> IDXBITS, idx = m & IDXMASK;
            bool later = false;
            for (int u = lane; u < d; u += 32) {
                unsigned m2 = g_meta[beg + u];
                if ((m2 >> IDXBITS) == dst && (m2 & IDXMASK) > idx) later = true;
            }
            if (!__any_sync(0xffffffffu, later)) {
                float wv = g_w[beg + t];
                if (lane == 0) dsum += wv;
                if (wv != 0.f) {
                    float4 hv = *(const float4*)(g_hw + (size_t)dst * D + lane * 4);
                    acc.x += wv * hv.x; acc.y += wv * hv.y;
                    acc.z += wv * hv.z; acc.w += wv * hv.w;
                }
            }
        }
    }

#pragma unroll
    for (int o = 16; o; o >>= 1) dsum += __shfl_xor_sync(0xffffffffu, dsum, o);
    float inv = 1.f / ((float)V + dsum);
    float4 S4 = *(const float4*)(g_S + lane * 4);
    float4 o4;
    o4.x = (S4.x + acc.x) * inv;
    o4.y = (S4.y + acc.y) * inv;
    o4.z = (S4.z + acc.z) * inv;
    o4.w = (S4.w + acc.w) * inv;
    *(float4*)(out + (size_t)row * D + lane * 4) = o4;
}

// ----------------------------------------------------------------------------
extern "C" void kernel_launch(void* const* d_in, const int* in_sizes, int n_in,
                              void* d_out, int out_size) {
    const float* h   = (const float*)d_in[0];
    const int*   ei  = (const int*)d_in[1];   // int64 or int32; detected at runtime
    const float* Wm  = (const float*)d_in[2];
    const float* att = (const float*)d_in[3];
    float* out = (float*)d_out;

    k_detect<<<1, 256>>>(ei);
    k_init<<<32, 256>>>();
    k_hw<<<V / 8, 128>>>(h, Wm);
    k_s<<<V / 8, 256>>>(att);
    k_colsum<<<V / 128, 128>>>();
    k_hist<<<E / 256, 256>>>(ei);
    k_scan<<<1, 1024>>>();
    k_scatter<<<E / 256, 256>>>(ei);
    k_row<<<V / 8, 256>>>(out);
}

// round 2
// speedup vs baseline: 1.3079x; 1.3079x over previous
#include <cuda_runtime.h>
#include <cuda_fp16.h>

#define V 8192
#define E 262144
#define D 128
#define CAP 192
#define IDXBITS 18
#define IDXMASK 0x3FFFFu

// ---------------- scratch (device globals; no allocations allowed) ----------
__device__ __half   g_hwh[V * D];     // h @ W^T in fp16 (2 MB, L2-resident)
__device__ float    g_s1[V];          // hw[v] . att[:128]   (fp32)
__device__ float    g_s2[V];          // hw[v] . att[128:]   (fp32)
__device__ float    g_S[D];           // column sum of hw    (fp32)
__device__ int      g_cnt[V];         // per-src bucket cursors
__device__ uint2    g_ew[V * CAP];    // { (dst<<18)|edge_idx , bits(w) }
__device__ int      g_is64;           // edge_index dtype flag

// =================== K1: init + int64/int32 detection ========================
// If edge_index is little-endian int64 (values < 2^13), every odd 32-bit word
// is zero. If int32, odd words are random src values.
__global__ void k_init(const int* __restrict__ e32) {
    int b = blockIdx.x, t = threadIdx.x;
    if (b == 0) {
        __shared__ int flag;
        if (t == 0) flag = 0;
        __syncthreads();
        if (e32[2 * t + 1] != 0) atomicExch(&flag, 1);
        __syncthreads();
        if (t == 0) g_is64 = (flag == 0) ? 1 : 0;
    } else if (b == 1) {
        if (t < D) g_S[t] = 0.f;
    } else {
        g_cnt[(b - 2) * 256 + t] = 0;
    }
}

// =================== K2: GEMM hw = h @ W^T + fused epilogue ==================
// Tile: 64 rows x 128 cols per block (grid 128). Threads (16x16), each 4x8.
// Epilogue: write fp16 hw, block-reduce colsum -> g_S (atomic), s1/s2 -> exact.
__global__ void __launch_bounds__(256) k_gemm(const float* __restrict__ h,
                                              const float* __restrict__ Wm,
                                              const float* __restrict__ att) {
    __shared__ float sh_A[32][65];    // [k][row], 64 rows
    __shared__ float sh_B[32][132];   // [k][col], 128 cols (16B-aligned rows)
    __shared__ float s1s[64], s2s[64], cs[128];

    int tid = threadIdx.x;
    int tx = tid & 15, ty = tid >> 4;     // tx: col group, ty: row group
    int row0 = blockIdx.x * 64;

    if (tid < 64) { s1s[tid] = 0.f; s2s[tid] = 0.f; }
    if (tid < 128) cs[tid] = 0.f;

    float acc[4][8];
#pragma unroll
    for (int r = 0; r < 4; r++)
#pragma unroll
        for (int c = 0; c < 8; c++) acc[r][c] = 0.f;

    for (int k0 = 0; k0 < 128; k0 += 32) {
        __syncthreads();
        // A: 64x32 floats = 512 float4, 2 per thread
#pragma unroll
        for (int i = 0; i < 2; i++) {
            int idx = tid + i * 256;
            int row = idx >> 3, q = idx & 7;
            float4 v = *(const float4*)(h + (size_t)(row0 + row) * D + k0 + q * 4);
            sh_A[q * 4 + 0][row] = v.x;
            sh_A[q * 4 + 1][row] = v.y;
            sh_A[q * 4 + 2][row] = v.z;
            sh_A[q * 4 + 3][row] = v.w;
        }
        // B: 128x32 floats = 1024 float4, 4 per thread  (W[col][k] row-major)
#pragma unroll
        for (int i = 0; i < 4; i++) {
            int idx = tid + i * 256;
            int col = idx >> 3, q = idx & 7;
            float4 v = *(const float4*)(Wm + (size_t)col * D + k0 + q * 4);
            sh_B[q * 4 + 0][col] = v.x;
            sh_B[q * 4 + 1][col] = v.y;
            sh_B[q * 4 + 2][col] = v.z;
            sh_B[q * 4 + 3][col] = v.w;
        }
        __syncthreads();
#pragma unroll
        for (int k = 0; k < 32; k++) {
            float a0 = sh_A[k][ty * 4 + 0];
            float a1 = sh_A[k][ty * 4 + 1];
            float a2 = sh_A[k][ty * 4 + 2];
            float a3 = sh_A[k][ty * 4 + 3];
            float4 b0 = *(const float4*)&sh_B[k][tx * 8];
            float4 b1 = *(const float4*)&sh_B[k][tx * 8 + 4];
            float bv[8] = {b0.x, b0.y, b0.z, b0.w, b1.x, b1.y, b1.z, b1.w};
#pragma unroll
            for (int c = 0; c < 8; c++) {
                acc[0][c] += a0 * bv[c];
                acc[1][c] += a1 * bv[c];
                acc[2][c] += a2 * bv[c];
                acc[3][c] += a3 * bv[c];
            }
        }
    }
    __syncthreads();

    // ---- epilogue ----
    // fp16 store: 8 halves (16B) per row per thread
#pragma unroll
    for (int r = 0; r < 4; r++) {
        int row = row0 + ty * 4 + r;
        __half2 h0 = __floats2half2_rn(acc[r][0], acc[r][1]);
        __half2 h1 = __floats2half2_rn(acc[r][2], acc[r][3]);
        __half2 h2 = __floats2half2_rn(acc[r][4], acc[r][5]);
        __half2 h3 = __floats2half2_rn(acc[r][6], acc[r][7]);
        uint4 u;
        u.x = *(unsigned*)&h0; u.y = *(unsigned*)&h1;
        u.z = *(unsigned*)&h2; u.w = *(unsigned*)&h3;
        *(uint4*)((__half*)g_hwh + (size_t)row * D + tx * 8) = u;
    }

    // s1/s2 partials (fp32): per-row dot with att halves over this thread's 8 cols
    float4 A1a = *(const float4*)(att + tx * 8);
    float4 A1b = *(const float4*)(att + tx * 8 + 4);
    float4 A2a = *(const float4*)(att + D + tx * 8);
    float4 A2b = *(const float4*)(att + D + tx * 8 + 4);
    float a1v[8] = {A1a.x, A1a.y, A1a.z, A1a.w, A1b.x, A1b.y, A1b.z, A1b.w};
    float a2v[8] = {A2a.x, A2a.y, A2a.z, A2a.w, A2b.x, A2b.y, A2b.z, A2b.w};
#pragma unroll
    for (int r = 0; r < 4; r++) {
        float p1 = 0.f, p2 = 0.f;
#pragma unroll
        for (int c = 0; c < 8; c++) { p1 += acc[r][c] * a1v[c]; p2 += acc[r][c] * a2v[c]; }
        atomicAdd(&s1s[ty * 4 + r], p1);
        atomicAdd(&s2s[ty * 4 + r], p2);
    }
    // column sums
#pragma unroll
    for (int c = 0; c < 8; c++) {
        float q = acc[0][c] + acc[1][c] + acc[2][c] + acc[3][c];
        atomicAdd(&cs[tx * 8 + c], q);
    }
    __syncthreads();
    if (tid < 64) { g_s1[row0 + tid] = s1s[tid]; g_s2[row0 + tid] = s2s[tid]; }
    if (tid < 128) atomicAdd(&g_S[tid], cs[tid]);
}

// =================== K3: per-edge logit + bucket scatter =====================
__global__ void k_scatter(const int* __restrict__ e32) {
    int e = blockIdx.x * blockDim.x + threadIdx.x;
    if (e >= E) return;
    int src, dst;
    if (g_is64) { src = e32[2 * e]; dst = e32[2 * (E + e)]; }
    else        { src = e32[e];     dst = e32[E + e]; }
    float a = g_s1[src] + g_s2[dst];
    a = a > 0.f ? a : 0.2f * a;                 // LeakyReLU(0.2)
    float w = expm1f(a);                        // exp(a) - 1
    int pos = atomicAdd(&g_cnt[src], 1);
    if (pos < CAP) {
        uint2 rec;
        rec.x = ((unsigned)dst << IDXBITS) | (unsigned)e;
        rec.y = __float_as_uint(w);
        g_ew[(size_t)src * CAP + pos] = rec;
    }
}

// =================== K4: dedup (last-write-wins) + gather + normalize ========
__global__ void __launch_bounds__(256) k_row(float* __restrict__ out) {
    __shared__ uint2 sm[8][CAP];
    int wid = threadIdx.x >> 5, lane = threadIdx.x & 31;
    int row = blockIdx.x * 8 + wid;
    int d = g_cnt[row];
    if (d > CAP) d = CAP;
    const uint2* bucket = g_ew + (size_t)row * CAP;

    for (int t = lane; t < d; t += 32) sm[wid][t] = bucket[t];
    __syncwarp();

    // pass 1: dedup — keep only max original-edge-index per dst
    float dsum = 0.f;
    for (int j = lane; j < d; j += 32) {
        unsigned mx = sm[wid][j].x;
        unsigned dst = mx >> IDXBITS, idx = mx & IDXMASK;
        bool kept = true;
        for (int t = 0; t < d; t++) {
            unsigned m2 = sm[wid][t].x;
            if ((m2 >> IDXBITS) == dst && (m2 & IDXMASK) > idx) { kept = false; break; }
        }
        if (!kept) sm[wid][j].y = 0u;           // zero the weight
        else dsum += __uint_as_float(sm[wid][j].y);
    }
    __syncwarp();

    // pass 2: fp16 row gathers (256B/row, L2-resident), rank-1 accumulate
    float4 acc = make_float4(0.f, 0.f, 0.f, 0.f);
    const __half* hw = (const __half*)g_hwh;
    int t = 0;
    for (; t + 4 <= d; t += 4) {
        uint2 m0 = sm[wid][t + 0], m1 = sm[wid][t + 1];
        uint2 m2 = sm[wid][t + 2], m3 = sm[wid][t + 3];
        uint2 v0 = *(const uint2*)(hw + (size_t)(m0.x >> IDXBITS) * D + lane * 4);
        uint2 v1 = *(const uint2*)(hw + (size_t)(m1.x >> IDXBITS) * D + lane * 4);
        uint2 v2 = *(const uint2*)(hw + (size_t)(m2.x >> IDXBITS) * D + lane * 4);
        uint2 v3 = *(const uint2*)(hw + (size_t)(m3.x >> IDXBITS) * D + lane * 4);
#define ACCUM(vv, mm) {                                           \
        float w_ = __uint_as_float((mm).y);                       \
        float2 f0_ = __half22float2(*(__half2*)&(vv).x);          \
        float2 f1_ = __half22float2(*(__half2*)&(vv).y);          \
        acc.x += w_ * f0_.x; acc.y += w_ * f0_.y;                 \
        acc.z += w_ * f1_.x; acc.w += w_ * f1_.y; }
        ACCUM(v0, m0); ACCUM(v1, m1); ACCUM(v2, m2); ACCUM(v3, m3);
    }
    for (; t < d; t++) {
        uint2 m = sm[wid][t];
        uint2 v = *(const uint2*)(hw + (size_t)(m.x >> IDXBITS) * D + lane * 4);
        ACCUM(v, m);
    }
#undef ACCUM

#pragma unroll
    for (int o = 16; o; o >>= 1) dsum += __shfl_xor_sync(0xffffffffu, dsum, o);
    float inv = 1.f / ((float)V + dsum);
    float4 S4 = *(const float4*)(g_S + lane * 4);
    float4 o4;
    o4.x = (S4.x + acc.x) * inv;
    o4.y = (S4.y + acc.y) * inv;
    o4.z = (S4.z + acc.z) * inv;
    o4.w = (S4.w + acc.w) * inv;
    *(float4*)(out + (size_t)row * D + lane * 4) = o4;
}

// ----------------------------------------------------------------------------
extern "C" void kernel_launch(void* const* d_in, const int* in_sizes, int n_in,
                              void* d_out, int out_size) {
    const float* h   = (const float*)d_in[0];
    const int*   ei  = (const int*)d_in[1];   // int64 or int32; detected at runtime
    const float* Wm  = (const float*)d_in[2];
    const float* att = (const float*)d_in[3];
    float* out = (float*)d_out;

    k_init<<<34, 256>>>(ei);
    k_gemm<<<V / 64, 256>>>(h, Wm, att);
    k_scatter<<<E / 256, 256>>>(ei);
    k_row<<<V / 8, 256>>>(out);
}

// round 3
// speedup vs baseline: 1.4054x; 1.0746x over previous
#include <cuda_runtime.h>
#include <cuda_fp16.h>

#define V 8192
#define E 262144
#define D 128
#define CAP 192
#define IDXBITS 18
#define IDXMASK 0x3FFFFu
#define RW 16   // rows (warps) per k_row block

// ---------------- scratch (device globals; no allocations allowed) ----------
__device__ __half   g_hwh[V * D];     // h @ W^T in fp16 (2 MB, L2-resident)
__device__ float    g_s1[V];          // hw[v] . att[:128]   (fp32)
__device__ float    g_s2[V];          // hw[v] . att[128:]   (fp32)
__device__ float    g_S[D];           // column sum of hw    (fp32)
__device__ int      g_cnt[V];         // per-src bucket cursors
__device__ uint2    g_ew[V * CAP];    // { (dst<<18)|edge_idx , bits(w) }
__device__ int      g_is64;           // edge_index dtype flag

// =================== K1: init + int64/int32 detection ========================
__global__ void k_init(const int* __restrict__ e32) {
    int b = blockIdx.x, t = threadIdx.x;
    if (b == 0) {
        __shared__ int flag;
        if (t == 0) flag = 0;
        __syncthreads();
        if (e32[2 * t + 1] != 0) atomicExch(&flag, 1);
        __syncthreads();
        if (t == 0) g_is64 = (flag == 0) ? 1 : 0;
    } else if (b == 1) {
        if (t < D) g_S[t] = 0.f;
    } else {
        g_cnt[(b - 2) * 256 + t] = 0;
    }
}

// =================== K2: GEMM hw = h @ W^T + fused epilogue ==================
__global__ void __launch_bounds__(256) k_gemm(const float* __restrict__ h,
                                              const float* __restrict__ Wm,
                                              const float* __restrict__ att) {
    __shared__ float sh_A[32][65];    // [k][row], 64 rows
    __shared__ float sh_B[32][132];   // [k][col], 128 cols
    __shared__ float s1s[64], s2s[64], cs[128];

    int tid = threadIdx.x;
    int tx = tid & 15, ty = tid >> 4;
    int row0 = blockIdx.x * 64;

    if (tid < 64) { s1s[tid] = 0.f; s2s[tid] = 0.f; }
    if (tid < 128) cs[tid] = 0.f;

    float acc[4][8];
#pragma unroll
    for (int r = 0; r < 4; r++)
#pragma unroll
        for (int c = 0; c < 8; c++) acc[r][c] = 0.f;

    for (int k0 = 0; k0 < 128; k0 += 32) {
        __syncthreads();
#pragma unroll
        for (int i = 0; i < 2; i++) {
            int idx = tid + i * 256;
            int row = idx >> 3, q = idx & 7;
            float4 v = *(const float4*)(h + (size_t)(row0 + row) * D + k0 + q * 4);
            sh_A[q * 4 + 0][row] = v.x;
            sh_A[q * 4 + 1][row] = v.y;
            sh_A[q * 4 + 2][row] = v.z;
            sh_A[q * 4 + 3][row] = v.w;
        }
#pragma unroll
        for (int i = 0; i < 4; i++) {
            int idx = tid + i * 256;
            int col = idx >> 3, q = idx & 7;
            float4 v = *(const float4*)(Wm + (size_t)col * D + k0 + q * 4);
            sh_B[q * 4 + 0][col] = v.x;
            sh_B[q * 4 + 1][col] = v.y;
            sh_B[q * 4 + 2][col] = v.z;
            sh_B[q * 4 + 3][col] = v.w;
        }
        __syncthreads();
#pragma unroll
        for (int k = 0; k < 32; k++) {
            float a0 = sh_A[k][ty * 4 + 0];
            float a1 = sh_A[k][ty * 4 + 1];
            float a2 = sh_A[k][ty * 4 + 2];
            float a3 = sh_A[k][ty * 4 + 3];
            float4 b0 = *(const float4*)&sh_B[k][tx * 8];
            float4 b1 = *(const float4*)&sh_B[k][tx * 8 + 4];
            float bv[8] = {b0.x, b0.y, b0.z, b0.w, b1.x, b1.y, b1.z, b1.w};
#pragma unroll
            for (int c = 0; c < 8; c++) {
                acc[0][c] += a0 * bv[c];
                acc[1][c] += a1 * bv[c];
                acc[2][c] += a2 * bv[c];
                acc[3][c] += a3 * bv[c];
            }
        }
    }
    __syncthreads();

#pragma unroll
    for (int r = 0; r < 4; r++) {
        int row = row0 + ty * 4 + r;
        __half2 h0 = __floats2half2_rn(acc[r][0], acc[r][1]);
        __half2 h1 = __floats2half2_rn(acc[r][2], acc[r][3]);
        __half2 h2 = __floats2half2_rn(acc[r][4], acc[r][5]);
        __half2 h3 = __floats2half2_rn(acc[r][6], acc[r][7]);
        uint4 u;
        u.x = *(unsigned*)&h0; u.y = *(unsigned*)&h1;
        u.z = *(unsigned*)&h2; u.w = *(unsigned*)&h3;
        *(uint4*)((__half*)g_hwh + (size_t)row * D + tx * 8) = u;
    }

    float4 A1a = *(const float4*)(att + tx * 8);
    float4 A1b = *(const float4*)(att + tx * 8 + 4);
    float4 A2a = *(const float4*)(att + D + tx * 8);
    float4 A2b = *(const float4*)(att + D + tx * 8 + 4);
    float a1v[8] = {A1a.x, A1a.y, A1a.z, A1a.w, A1b.x, A1b.y, A1b.z, A1b.w};
    float a2v[8] = {A2a.x, A2a.y, A2a.z, A2a.w, A2b.x, A2b.y, A2b.z, A2b.w};
#pragma unroll
    for (int r = 0; r < 4; r++) {
        float p1 = 0.f, p2 = 0.f;
#pragma unroll
        for (int c = 0; c < 8; c++) { p1 += acc[r][c] * a1v[c]; p2 += acc[r][c] * a2v[c]; }
        atomicAdd(&s1s[ty * 4 + r], p1);
        atomicAdd(&s2s[ty * 4 + r], p2);
    }
#pragma unroll
    for (int c = 0; c < 8; c++) {
        float q = acc[0][c] + acc[1][c] + acc[2][c] + acc[3][c];
        atomicAdd(&cs[tx * 8 + c], q);
    }
    __syncthreads();
    if (tid < 64) { g_s1[row0 + tid] = s1s[tid]; g_s2[row0 + tid] = s2s[tid]; }
    if (tid < 128) atomicAdd(&g_S[tid], cs[tid]);
}

// =================== K3: per-edge logit + bucket scatter =====================
__global__ void k_scatter(const int* __restrict__ e32) {
    int e = blockIdx.x * blockDim.x + threadIdx.x;
    if (e >= E) return;
    int src, dst;
    if (g_is64) { src = e32[2 * e]; dst = e32[2 * (E + e)]; }
    else        { src = e32[e];     dst = e32[E + e]; }
    float a = g_s1[src] + g_s2[dst];
    a = a > 0.f ? a : 0.2f * a;                 // LeakyReLU(0.2)
    float w = expm1f(a);                        // exp(a) - 1
    int pos = atomicAdd(&g_cnt[src], 1);
    if (pos < CAP) {
        uint2 rec;
        rec.x = ((unsigned)dst << IDXBITS) | (unsigned)e;
        rec.y = __float_as_uint(w);
        g_ew[(size_t)src * CAP + pos] = rec;
    }
}

// =================== K4: dedup + wide gather + normalize =====================
// One warp per row. Lanes 0-15 serve edge A of a pair, lanes 16-31 edge B;
// each lane loads 16B (8 halves) of the gathered row -> LDG.128, MLP=4 pairs.
__global__ void __launch_bounds__(32 * RW) k_row(float* __restrict__ out) {
    __shared__ uint2 sm[RW][CAP + 8];
    int wid = threadIdx.x >> 5, lane = threadIdx.x & 31;
    int row = blockIdx.x * RW + wid;
    int d = g_cnt[row];
    if (d > CAP) d = CAP;
    int dpad = (d + 7) & ~7;
    const uint2* bucket = g_ew + (size_t)row * CAP;

    for (int t = lane; t < dpad; t += 32)
        sm[wid][t] = (t < d) ? bucket[t] : make_uint2(0u, 0u);
    __syncwarp();

    // pass 1: dedup — keep only max original-edge-index per dst (last-write-wins)
    float dsum = 0.f;
    for (int j = lane; j < d; j += 32) {
        unsigned mx = sm[wid][j].x;
        unsigned dst = mx >> IDXBITS, idx = mx & IDXMASK;
        bool kept = true;
        for (int t = 0; t < d; t++) {
            unsigned m2 = sm[wid][t].x;
            if ((m2 >> IDXBITS) == dst && (m2 & IDXMASK) > idx) { kept = false; break; }
        }
        if (!kept) sm[wid][j].y = 0u;
        else dsum += __uint_as_float(sm[wid][j].y);
    }
    __syncwarp();

    // pass 2: 2 edges per warp step, 16B per lane, 4 pairs unrolled
    float acc[8];
#pragma unroll
    for (int i = 0; i < 8; i++) acc[i] = 0.f;
    int half = lane >> 4;          // which edge of the pair
    int cl = (lane & 15) * 8;      // column base (8 halves)
    const __half* hw = g_hwh;

    for (int t = 0; t < dpad; t += 8) {
#pragma unroll
        for (int p = 0; p < 4; p++) {
            uint2 m = sm[wid][t + 2 * p + half];
            float w = __uint_as_float(m.y);
            uint4 v = *(const uint4*)(hw + (size_t)(m.x >> IDXBITS) * D + cl);
            float2 f0 = __half22float2(*(__half2*)&v.x);
            float2 f1 = __half22float2(*(__half2*)&v.y);
            float2 f2 = __half22float2(*(__half2*)&v.z);
            float2 f3 = __half22float2(*(__half2*)&v.w);
            acc[0] += w * f0.x; acc[1] += w * f0.y;
            acc[2] += w * f1.x; acc[3] += w * f1.y;
            acc[4] += w * f2.x; acc[5] += w * f2.y;
            acc[6] += w * f3.x; acc[7] += w * f3.y;
        }
    }

#pragma unroll
    for (int i = 0; i < 8; i++) acc[i] += __shfl_xor_sync(0xffffffffu, acc[i], 16);
#pragma unroll
    for (int o = 16; o; o >>= 1) dsum += __shfl_xor_sync(0xffffffffu, dsum, o);

    float inv = 1.f / ((float)V + dsum);
    if (lane < 16) {
        float4 Sa = *(const float4*)(g_S + cl);
        float4 Sb = *(const float4*)(g_S + cl + 4);
        float4 o0, o1;
        o0.x = (Sa.x + acc[0]) * inv; o0.y = (Sa.y + acc[1]) * inv;
        o0.z = (Sa.z + acc[2]) * inv; o0.w = (Sa.w + acc[3]) * inv;
        o1.x = (Sb.x + acc[4]) * inv; o1.y = (Sb.y + acc[5]) * inv;
        o1.z = (Sb.z + acc[6]) * inv; o1.w = (Sb.w + acc[7]) * inv;
        *(float4*)(out + (size_t)row * D + cl) = o0;
        *(float4*)(out + (size_t)row * D + cl + 4) = o1;
    }
}

// ----------------------------------------------------------------------------
extern "C" void kernel_launch(void* const* d_in, const int* in_sizes, int n_in,
                              void* d_out, int out_size) {
    const float* h   = (const float*)d_in[0];
    const int*   ei  = (const int*)d_in[1];
    const float* Wm  = (const float*)d_in[2];
    const float* att = (const float*)d_in[3];
    float* out = (float*)d_out;

    k_init<<<34, 256>>>(ei);
    k_gemm<<<V / 64, 256>>>(h, Wm, att);
    k_scatter<<<E / 256, 256>>>(ei);
    k_row<<<V / RW, 32 * RW>>>(out);
}